// round 1
// baseline (speedup 1.0000x reference)
#include <cuda_runtime.h>
#include <math.h>

#define T_ 200
#define N_ 256
#define H_ 128
#define G_ 512   // 4*H
#define V_ 50000

// Scratch (static device globals — allocation-free per harness rules)
__device__ float g_wx[(size_t)T_ * N_ * G_];   // 104.8 MB: Wx[t,n,j] = emb[seq[t,n]]@W + b
__device__ float g_hmean[N_ * H_];             // h_mean[n,k]

__device__ __forceinline__ float sigf(float x) { return 1.0f / (1.0f + expf(-x)); }

// ---------------------------------------------------------------------------
// Kernel 1: Wx[t*N+n, :] = emb[seq[t,n], :] @ W + b   (gather-GEMM, M=51200,N=512,K=128)
// Tile 64x64, K loaded in full. Block = 256 threads (16x16, 4x4 register tile).
// ---------------------------------------------------------------------------
__global__ void __launch_bounds__(256) wx_kernel(const int* __restrict__ seq,
                                                 const float* __restrict__ emb,
                                                 const float* __restrict__ W,
                                                 const float* __restrict__ b)
{
    extern __shared__ float sm[];
    float* As = sm;                 // [64][132] padded
    float* Bs = sm + 64 * 132;      // [128][64]
    int*   ridx = (int*)(Bs + 128 * 64);  // [64]

    const int tid = threadIdx.x;
    const int bc = blockIdx.x;      // col tile (0..7)
    const int br = blockIdx.y;      // row tile (0..799)

    if (tid < 64) ridx[tid] = seq[br * 64 + tid];
    __syncthreads();

    // Load A tile: 64 rows x 128 cols, gathered from embedding table (float4)
    for (int p = tid; p < 64 * 32; p += 256) {
        int r = p >> 5, kq = p & 31;
        float4 v = *(const float4*)(emb + (size_t)ridx[r] * H_ + kq * 4);
        float* dst = As + r * 132 + kq * 4;
        dst[0] = v.x; dst[1] = v.y; dst[2] = v.z; dst[3] = v.w;
    }
    // Load B tile: W[0:128, bc*64 : bc*64+64]
    for (int p = tid; p < 128 * 16; p += 256) {
        int k = p >> 4, cq = p & 15;
        *(float4*)(Bs + k * 64 + cq * 4) = *(const float4*)(W + k * G_ + bc * 64 + cq * 4);
    }
    __syncthreads();

    const int ty = tid >> 4, tx = tid & 15;
    const int r0 = ty * 4, c0 = tx * 4;
    float acc[4][4];
    #pragma unroll
    for (int i = 0; i < 4; i++)
        #pragma unroll
        for (int j = 0; j < 4; j++) acc[i][j] = 0.0f;

    #pragma unroll 8
    for (int k = 0; k < 128; ++k) {
        float a0 = As[(r0 + 0) * 132 + k];
        float a1 = As[(r0 + 1) * 132 + k];
        float a2 = As[(r0 + 2) * 132 + k];
        float a3 = As[(r0 + 3) * 132 + k];
        float4 bv = *(float4*)(Bs + k * 64 + c0);
        acc[0][0] += a0 * bv.x; acc[0][1] += a0 * bv.y; acc[0][2] += a0 * bv.z; acc[0][3] += a0 * bv.w;
        acc[1][0] += a1 * bv.x; acc[1][1] += a1 * bv.y; acc[1][2] += a1 * bv.z; acc[1][3] += a1 * bv.w;
        acc[2][0] += a2 * bv.x; acc[2][1] += a2 * bv.y; acc[2][2] += a2 * bv.z; acc[2][3] += a2 * bv.w;
        acc[3][0] += a3 * bv.x; acc[3][1] += a3 * bv.y; acc[3][2] += a3 * bv.z; acc[3][3] += a3 * bv.w;
    }

    float4 bias = *(const float4*)(b + bc * 64 + c0);
    #pragma unroll
    for (int i = 0; i < 4; i++) {
        int row = br * 64 + r0 + i;
        float4 o;
        o.x = acc[i][0] + bias.x;
        o.y = acc[i][1] + bias.y;
        o.z = acc[i][2] + bias.z;
        o.w = acc[i][3] + bias.w;
        *(float4*)(g_wx + (size_t)row * G_ + bc * 64 + c0) = o;
    }
}

// ---------------------------------------------------------------------------
// Kernel 2: recurrence. One CTA per n, histories resident in smem (204.8 KB).
// 256 threads: [0,128) own h-dims, [128,256) own c-dims for aggregation;
// GEMV: each thread computes 2 of the 512 gate columns (float2 U loads, L2-hot).
// ---------------------------------------------------------------------------
__global__ void __launch_bounds__(256, 1) rec_kernel(const float* __restrict__ mask,
                                                     const float* __restrict__ topo,
                                                     const float* __restrict__ U)
{
    extern __shared__ float sm[];
    float* h_hist = sm;                        // [200][128]
    float* c_hist = h_hist + T_ * H_;          // [200][128]
    float* hs     = c_hist + T_ * H_;          // [128]
    float* cs     = hs + H_;                   // [128]
    float* gates  = cs + H_;                   // [512]
    float* tw     = gates + G_;                // [200]

    const int n = blockIdx.x;
    const int tid = threadIdx.x;

    // zero both histories
    for (int i = tid; i < 2 * T_ * H_; i += 256) h_hist[i] = 0.0f;
    __syncthreads();

    float hacc = 0.0f, lensum = 0.0f;
    const int col = tid & 127;
    const float* hist = (tid < 128) ? h_hist : c_hist;
    const float2* Up = ((const float2*)U) + tid;   // U[i*512 + 2*tid]

    for (int t = 0; t < T_; ++t) {
        // topology weights for this (t, n)
        const float* trow = topo + ((size_t)t * N_ + n) * T_;
        for (int i = tid; i < t; i += 256) tw[i] = trow[i];
        __syncthreads();

        // masked aggregation over stored states (only t' < t are nonzero)
        float acc = 0.0f;
        #pragma unroll 4
        for (int tp = 0; tp < t; ++tp) acc += tw[tp] * hist[tp * H_ + col];
        if (tid < 128) hs[col] = acc; else cs[col] = acc;
        __syncthreads();

        // gates = hs @ U + Wx[t,n,:]   (each thread: cols 2*tid, 2*tid+1)
        float g0 = 0.0f, g1 = 0.0f;
        #pragma unroll 8
        for (int i = 0; i < H_; ++i) {
            float hv = hs[i];
            float2 u = Up[i * (G_ / 2)];
            g0 += hv * u.x;
            g1 += hv * u.y;
        }
        const float* wrow = g_wx + ((size_t)t * N_ + n) * G_;
        int j = tid * 2;
        gates[j]     = g0 + wrow[j];
        gates[j + 1] = g1 + wrow[j + 1];
        __syncthreads();

        // elementwise LSTM cell (threads 0..127, one h-dim each)
        if (tid < 128) {
            float m  = mask[t * N_ + n];
            float ig = sigf(gates[tid]);
            float fg = sigf(gates[128 + tid]);
            float og = sigf(gates[256 + tid]);
            float gg = tanhf(gates[384 + tid]);
            float c  = m * (fg * cs[tid] + ig * gg);
            float h  = m * (og * tanhf(c));
            h_hist[t * H_ + tid] = h;
            c_hist[t * H_ + tid] = c;
            hacc += m * h;
            lensum += m;
        }
        __syncthreads();
    }

    if (tid < 128) g_hmean[n * H_ + tid] = hacc / lensum;
}

// ---------------------------------------------------------------------------
// Kernel 3: out[n, v] = h_mean[n,:] @ W_out[:, v] + b_out[v]
// M=256, N=50000, K=128. Tile 64x64, col guard at 50000.
// ---------------------------------------------------------------------------
__global__ void __launch_bounds__(256) out_kernel(const float* __restrict__ Wout,
                                                  const float* __restrict__ bout,
                                                  float* __restrict__ out)
{
    extern __shared__ float sm[];
    float* As = sm;                 // [64][132]
    float* Bs = sm + 64 * 132;      // [128][64]

    const int tid = threadIdx.x;
    const int bc = blockIdx.x;      // col tile (0..781)
    const int br = blockIdx.y;      // row tile (0..3)
    const int cbase = bc * 64;

    // A tile: h_mean rows
    for (int p = tid; p < 64 * 32; p += 256) {
        int r = p >> 5, kq = p & 31;
        float4 v = *(const float4*)(g_hmean + (size_t)(br * 64 + r) * H_ + kq * 4);
        float* dst = As + r * 132 + kq * 4;
        dst[0] = v.x; dst[1] = v.y; dst[2] = v.z; dst[3] = v.w;
    }
    // B tile: W_out[0:128, cbase:cbase+64] with column guard (50000 % 4 == 0)
    for (int p = tid; p < 128 * 16; p += 256) {
        int k = p >> 4, cq = p & 15;
        int c = cbase + cq * 4;
        float4 v = make_float4(0.f, 0.f, 0.f, 0.f);
        if (c < V_) v = *(const float4*)(Wout + (size_t)k * V_ + c);
        *(float4*)(Bs + k * 64 + cq * 4) = v;
    }
    __syncthreads();

    const int ty = tid >> 4, tx = tid & 15;
    const int r0 = ty * 4, c0 = tx * 4;
    float acc[4][4];
    #pragma unroll
    for (int i = 0; i < 4; i++)
        #pragma unroll
        for (int j = 0; j < 4; j++) acc[i][j] = 0.0f;

    #pragma unroll 8
    for (int k = 0; k < 128; ++k) {
        float a0 = As[(r0 + 0) * 132 + k];
        float a1 = As[(r0 + 1) * 132 + k];
        float a2 = As[(r0 + 2) * 132 + k];
        float a3 = As[(r0 + 3) * 132 + k];
        float4 bv = *(float4*)(Bs + k * 64 + c0);
        acc[0][0] += a0 * bv.x; acc[0][1] += a0 * bv.y; acc[0][2] += a0 * bv.z; acc[0][3] += a0 * bv.w;
        acc[1][0] += a1 * bv.x; acc[1][1] += a1 * bv.y; acc[1][2] += a1 * bv.z; acc[1][3] += a1 * bv.w;
        acc[2][0] += a2 * bv.x; acc[2][1] += a2 * bv.y; acc[2][2] += a2 * bv.z; acc[2][3] += a2 * bv.w;
        acc[3][0] += a3 * bv.x; acc[3][1] += a3 * bv.y; acc[3][2] += a3 * bv.z; acc[3][3] += a3 * bv.w;
    }

    int c = cbase + c0;
    if (c < V_) {
        float4 bias = *(const float4*)(bout + c);
        #pragma unroll
        for (int i = 0; i < 4; i++) {
            int row = br * 64 + r0 + i;
            float4 o;
            o.x = acc[i][0] + bias.x;
            o.y = acc[i][1] + bias.y;
            o.z = acc[i][2] + bias.z;
            o.w = acc[i][3] + bias.w;
            *(float4*)(out + (size_t)row * V_ + c) = o;
        }
    }
}

// ---------------------------------------------------------------------------
extern "C" void kernel_launch(void* const* d_in, const int* in_sizes, int n_in,
                              void* d_out, int out_size)
{
    const int*   seq  = (const int*)d_in[0];
    const float* mask = (const float*)d_in[1];
    const float* topo = (const float*)d_in[2];
    const float* W    = (const float*)d_in[3];
    const float* U    = (const float*)d_in[4];
    const float* b    = (const float*)d_in[5];
    const float* emb  = (const float*)d_in[6];
    const float* Wout = (const float*)d_in[7];
    const float* bout = (const float*)d_in[8];
    float* out = (float*)d_out;

    const int smem_gemm = (64 * 132 + 128 * 64 + 64) * 4;         // 66,816 B
    const int smem_rec  = (2 * T_ * H_ + 2 * H_ + G_ + T_) * 4;   // 208,672 B

    cudaFuncSetAttribute(wx_kernel,  cudaFuncAttributeMaxDynamicSharedMemorySize, smem_gemm);
    cudaFuncSetAttribute(out_kernel, cudaFuncAttributeMaxDynamicSharedMemorySize, smem_gemm);
    cudaFuncSetAttribute(rec_kernel, cudaFuncAttributeMaxDynamicSharedMemorySize, smem_rec);

    // 1. Wx = emb[seq] @ W + b   -> g_wx
    wx_kernel<<<dim3(G_ / 64, (T_ * N_) / 64), 256, smem_gemm>>>(seq, emb, W, b);

    // 2. recurrence -> g_hmean
    rec_kernel<<<N_, 256, smem_rec>>>(mask, topo, U);

    // 3. out = h_mean @ W_out + b_out
    out_kernel<<<dim3((V_ + 63) / 64, N_ / 64), 256, smem_gemm>>>(Wout, bout, out);
}

// round 2
// speedup vs baseline: 1.1830x; 1.1830x over previous
#include <cuda_runtime.h>
#include <math.h>

#define T_ 200
#define N_ 256
#define H_ 128
#define G_ 512   // 4*H
#define V_ 50000

#define TB 10          // time-block size (divides 200)
#define NBLK (T_/TB)   // 20 blocks
#define NB 4           // sequences per CTA
#define GCTA (N_/NB)   // 64 CTAs
#define RTHREADS 512

// Scratch (static device globals — allocation-free per harness rules)
__device__ float g_wx[(size_t)T_ * N_ * G_];    // 104.8 MB: Wx[t,n,j]
__device__ float g_hhist[(size_t)T_ * N_ * H_]; // 26.2 MB
__device__ float g_chist[(size_t)T_ * N_ * H_]; // 26.2 MB
__device__ float g_hmean[N_ * H_];

__device__ __forceinline__ float sigf(float x) { return 1.0f / (1.0f + expf(-x)); }

// ---------------------------------------------------------------------------
// Kernel 1: Wx[t*N+n, :] = emb[seq[t,n], :] @ W + b  (unchanged from R1)
// ---------------------------------------------------------------------------
__global__ void __launch_bounds__(256) wx_kernel(const int* __restrict__ seq,
                                                 const float* __restrict__ emb,
                                                 const float* __restrict__ W,
                                                 const float* __restrict__ b)
{
    extern __shared__ float sm[];
    float* As = sm;                 // [64][132]
    float* Bs = sm + 64 * 132;      // [128][64]
    int*   ridx = (int*)(Bs + 128 * 64);

    const int tid = threadIdx.x;
    const int bc = blockIdx.x;
    const int br = blockIdx.y;

    if (tid < 64) ridx[tid] = seq[br * 64 + tid];
    __syncthreads();

    for (int p = tid; p < 64 * 32; p += 256) {
        int r = p >> 5, kq = p & 31;
        float4 v = *(const float4*)(emb + (size_t)ridx[r] * H_ + kq * 4);
        float* dst = As + r * 132 + kq * 4;
        dst[0] = v.x; dst[1] = v.y; dst[2] = v.z; dst[3] = v.w;
    }
    for (int p = tid; p < 128 * 16; p += 256) {
        int k = p >> 4, cq = p & 15;
        *(float4*)(Bs + k * 64 + cq * 4) = *(const float4*)(W + k * G_ + bc * 64 + cq * 4);
    }
    __syncthreads();

    const int ty = tid >> 4, tx = tid & 15;
    const int r0 = ty * 4, c0 = tx * 4;
    float acc[4][4];
    #pragma unroll
    for (int i = 0; i < 4; i++)
        #pragma unroll
        for (int j = 0; j < 4; j++) acc[i][j] = 0.0f;

    #pragma unroll 8
    for (int k = 0; k < 128; ++k) {
        float a0 = As[(r0 + 0) * 132 + k];
        float a1 = As[(r0 + 1) * 132 + k];
        float a2 = As[(r0 + 2) * 132 + k];
        float a3 = As[(r0 + 3) * 132 + k];
        float4 bv = *(float4*)(Bs + k * 64 + c0);
        acc[0][0] += a0 * bv.x; acc[0][1] += a0 * bv.y; acc[0][2] += a0 * bv.z; acc[0][3] += a0 * bv.w;
        acc[1][0] += a1 * bv.x; acc[1][1] += a1 * bv.y; acc[1][2] += a1 * bv.z; acc[1][3] += a1 * bv.w;
        acc[2][0] += a2 * bv.x; acc[2][1] += a2 * bv.y; acc[2][2] += a2 * bv.z; acc[2][3] += a2 * bv.w;
        acc[3][0] += a3 * bv.x; acc[3][1] += a3 * bv.y; acc[3][2] += a3 * bv.z; acc[3][3] += a3 * bv.w;
    }

    float4 bias = *(const float4*)(b + bc * 64 + c0);
    #pragma unroll
    for (int i = 0; i < 4; i++) {
        int row = br * 64 + r0 + i;
        float4 o;
        o.x = acc[i][0] + bias.x;
        o.y = acc[i][1] + bias.y;
        o.z = acc[i][2] + bias.z;
        o.w = acc[i][3] + bias.w;
        *(float4*)(g_wx + (size_t)row * G_ + bc * 64 + c0) = o;
    }
}

// ---------------------------------------------------------------------------
// Kernel 2: recurrence, v2.
// 64 CTAs x 512 thr; each CTA owns NB=4 sequences. Gates = (4x128)@(128x512)
// GEMM per step (U from L2, 4x reuse). History in global; per-block prologue
// GEMM computes pre-block aggregation P with TB-fold reuse; in-block taps
// come from a smem ring.
// ---------------------------------------------------------------------------
__global__ void __launch_bounds__(RTHREADS, 1) rec2_kernel(const float* __restrict__ mask,
                                                           const float* __restrict__ topo,
                                                           const float* __restrict__ U)
{
    extern __shared__ float sm[];
    // layout (floats): topoT[4][200][12] | Ph[TB][4][128] | Pc | ringh | ringc
    //                  | hsumT[128][4] | csum[4][128] | gates[4][512]
    float* topoT = sm;                          // 9600
    float* Ph    = topoT + 4 * 200 * 12;        // 5120
    float* Pc    = Ph + TB * NB * H_;           // 5120
    float* ringh = Pc + TB * NB * H_;           // 5120
    float* ringc = ringh + TB * NB * H_;        // 5120
    float* hsumT = ringc + TB * NB * H_;        // 512  ([i][j] for float4 reads)
    float* csum  = hsumT + H_ * NB;             // 512  ([j][h])
    float* gates = csum + NB * H_;              // 2048

    const int tid  = threadIdx.x;
    const int wid  = tid >> 5;
    const int lane = tid & 31;
    const int b    = blockIdx.x;
    const int n0   = b * NB;

    const int ej = tid >> 7;      // elementwise identity: sequence j
    const int eh = tid & 127;     // h-dim
    float hacc = 0.0f, lsum = 0.0f;

    for (int k = 0; k < NBLK; ++k) {
        const int t0 = k * TB;
        const int plen = t0 + TB;

        // ---- load topo prefix for this block: topoT[j][tp][tt], tp < plen ----
        // row (tt,j): topo[(t0+tt)*N + n0+j][0..plen)
        for (int r = wid; r < TB * NB; r += 16) {
            int tt = r / NB, j = r % NB;
            const float* src = topo + ((size_t)(t0 + tt) * N_ + (n0 + j)) * T_;
            for (int tp = lane; tp < plen; tp += 32)
                topoT[(j * 200 + tp) * 12 + tt] = src[tp];
        }
        __syncthreads();

        // ---- prologue: P[tt][j][:] = sum_{tp<t0} topo * hist ----
        if (k == 0) {
            for (int i = tid; i < 2 * TB * NB * H_; i += RTHREADS) Ph[i] = 0.0f;
        } else {
            // warp -> (j, h/c, dim-half); lane -> 2 dims (float2)
            const int j    = wid >> 2;
            const int hc   = (wid >> 1) & 1;
            const int half = wid & 1;
            const float* hist = hc ? g_chist : g_hhist;
            float* P = hc ? Pc : Ph;
            const int d = half * 64 + lane * 2;
            float acc[TB][2];
            #pragma unroll
            for (int s = 0; s < TB; s++) { acc[s][0] = 0.0f; acc[s][1] = 0.0f; }
            const float* tbase = topoT + (size_t)j * 200 * 12;
            #pragma unroll 2
            for (int tp = 0; tp < t0; ++tp) {
                float2 hv = *(const float2*)(hist + ((size_t)tp * N_ + n0 + j) * H_ + d);
                const float* tr = tbase + tp * 12;
                float4 w0 = *(const float4*)(tr);
                float4 w1 = *(const float4*)(tr + 4);
                float2 w2 = *(const float2*)(tr + 8);
                float w[TB] = {w0.x, w0.y, w0.z, w0.w, w1.x, w1.y, w1.z, w1.w, w2.x, w2.y};
                #pragma unroll
                for (int s = 0; s < TB; s++) {
                    acc[s][0] += w[s] * hv.x;
                    acc[s][1] += w[s] * hv.y;
                }
            }
            #pragma unroll
            for (int s = 0; s < TB; s++)
                *(float2*)(P + (s * NB + j) * H_ + d) = make_float2(acc[s][0], acc[s][1]);
        }
        __syncthreads();

        // ---- sequential steps within the block ----
        for (int tt = 0; tt < TB; ++tt) {
            const int t = t0 + tt;

            // 1. h_sum / c_sum = P + in-block taps (thread = (ej, eh))
            {
                float ah = Ph[(tt * NB + ej) * H_ + eh];
                float ac = Pc[(tt * NB + ej) * H_ + eh];
                const float* tb2 = topoT + ((size_t)ej * 200 + t0) * 12 + tt;
                for (int s = 0; s < tt; ++s) {
                    float w = tb2[s * 12];
                    ah += w * ringh[(s * NB + ej) * H_ + eh];
                    ac += w * ringc[(s * NB + ej) * H_ + eh];
                }
                hsumT[eh * NB + ej] = ah;   // transposed for float4 reads
                csum[ej * H_ + eh] = ac;
            }
            __syncthreads();

            // 2. gates[j][g] = sum_i hsum[j][i] * U[i][g] + wx  (thread = col g)
            {
                float a0 = 0.f, a1 = 0.f, a2 = 0.f, a3 = 0.f;
                const float* Ucol = U + tid;
                #pragma unroll 4
                for (int i = 0; i < H_; ++i) {
                    float4 hv = *(const float4*)(hsumT + i * NB);
                    float u = Ucol[(size_t)i * G_];
                    a0 += hv.x * u; a1 += hv.y * u; a2 += hv.z * u; a3 += hv.w * u;
                }
                const float* wrow = g_wx + ((size_t)t * N_ + n0) * G_;
                gates[0 * G_ + tid] = a0 + wrow[0 * G_ + tid];
                gates[1 * G_ + tid] = a1 + wrow[1 * G_ + tid];
                gates[2 * G_ + tid] = a2 + wrow[2 * G_ + tid];
                gates[3 * G_ + tid] = a3 + wrow[3 * G_ + tid];
            }
            __syncthreads();

            // 3. elementwise cell (thread = (ej, eh))
            {
                float m  = mask[t * N_ + n0 + ej];
                float ig = sigf(gates[ej * G_ + eh]);
                float fg = sigf(gates[ej * G_ + 128 + eh]);
                float og = sigf(gates[ej * G_ + 256 + eh]);
                float gg = tanhf(gates[ej * G_ + 384 + eh]);
                float c  = m * (fg * csum[ej * H_ + eh] + ig * gg);
                float h  = m * (og * tanhf(c));
                ringh[(tt * NB + ej) * H_ + eh] = h;
                ringc[(tt * NB + ej) * H_ + eh] = c;
                g_hhist[((size_t)t * N_ + n0 + ej) * H_ + eh] = h;
                g_chist[((size_t)t * N_ + n0 + ej) * H_ + eh] = c;
                hacc += m * h;
                lsum += m;
            }
            __syncthreads();
        }
    }

    g_hmean[(n0 + ej) * H_ + eh] = hacc / lsum;
}

// ---------------------------------------------------------------------------
// Kernel 3: out[n, v] = h_mean @ W_out + b_out  (unchanged from R1)
// ---------------------------------------------------------------------------
__global__ void __launch_bounds__(256) out_kernel(const float* __restrict__ Wout,
                                                  const float* __restrict__ bout,
                                                  float* __restrict__ out)
{
    extern __shared__ float sm[];
    float* As = sm;                 // [64][132]
    float* Bs = sm + 64 * 132;      // [128][64]

    const int tid = threadIdx.x;
    const int bc = blockIdx.x;
    const int br = blockIdx.y;
    const int cbase = bc * 64;

    for (int p = tid; p < 64 * 32; p += 256) {
        int r = p >> 5, kq = p & 31;
        float4 v = *(const float4*)(g_hmean + (size_t)(br * 64 + r) * H_ + kq * 4);
        float* dst = As + r * 132 + kq * 4;
        dst[0] = v.x; dst[1] = v.y; dst[2] = v.z; dst[3] = v.w;
    }
    for (int p = tid; p < 128 * 16; p += 256) {
        int k = p >> 4, cq = p & 15;
        int c = cbase + cq * 4;
        float4 v = make_float4(0.f, 0.f, 0.f, 0.f);
        if (c < V_) v = *(const float4*)(Wout + (size_t)k * V_ + c);
        *(float4*)(Bs + k * 64 + cq * 4) = v;
    }
    __syncthreads();

    const int ty = tid >> 4, tx = tid & 15;
    const int r0 = ty * 4, c0 = tx * 4;
    float acc[4][4];
    #pragma unroll
    for (int i = 0; i < 4; i++)
        #pragma unroll
        for (int j = 0; j < 4; j++) acc[i][j] = 0.0f;

    #pragma unroll 8
    for (int k = 0; k < 128; ++k) {
        float a0 = As[(r0 + 0) * 132 + k];
        float a1 = As[(r0 + 1) * 132 + k];
        float a2 = As[(r0 + 2) * 132 + k];
        float a3 = As[(r0 + 3) * 132 + k];
        float4 bv = *(float4*)(Bs + k * 64 + c0);
        acc[0][0] += a0 * bv.x; acc[0][1] += a0 * bv.y; acc[0][2] += a0 * bv.z; acc[0][3] += a0 * bv.w;
        acc[1][0] += a1 * bv.x; acc[1][1] += a1 * bv.y; acc[1][2] += a1 * bv.z; acc[1][3] += a1 * bv.w;
        acc[2][0] += a2 * bv.x; acc[2][1] += a2 * bv.y; acc[2][2] += a2 * bv.z; acc[2][3] += a2 * bv.w;
        acc[3][0] += a3 * bv.x; acc[3][1] += a3 * bv.y; acc[3][2] += a3 * bv.z; acc[3][3] += a3 * bv.w;
    }

    int c = cbase + c0;
    if (c < V_) {
        float4 bias = *(const float4*)(bout + c);
        #pragma unroll
        for (int i = 0; i < 4; i++) {
            int row = br * 64 + r0 + i;
            float4 o;
            o.x = acc[i][0] + bias.x;
            o.y = acc[i][1] + bias.y;
            o.z = acc[i][2] + bias.z;
            o.w = acc[i][3] + bias.w;
            *(float4*)(out + (size_t)row * V_ + c) = o;
        }
    }
}

// ---------------------------------------------------------------------------
extern "C" void kernel_launch(void* const* d_in, const int* in_sizes, int n_in,
                              void* d_out, int out_size)
{
    const int*   seq  = (const int*)d_in[0];
    const float* mask = (const float*)d_in[1];
    const float* topo = (const float*)d_in[2];
    const float* W    = (const float*)d_in[3];
    const float* U    = (const float*)d_in[4];
    const float* b    = (const float*)d_in[5];
    const float* emb  = (const float*)d_in[6];
    const float* Wout = (const float*)d_in[7];
    const float* bout = (const float*)d_in[8];
    float* out = (float*)d_out;

    const int smem_gemm = (64 * 132 + 128 * 64 + 64) * 4;
    const int smem_rec  = (4 * 200 * 12 + 4 * TB * NB * H_ + H_ * NB + NB * H_ + NB * G_) * 4;

    cudaFuncSetAttribute(wx_kernel,   cudaFuncAttributeMaxDynamicSharedMemorySize, smem_gemm);
    cudaFuncSetAttribute(out_kernel,  cudaFuncAttributeMaxDynamicSharedMemorySize, smem_gemm);
    cudaFuncSetAttribute(rec2_kernel, cudaFuncAttributeMaxDynamicSharedMemorySize, smem_rec);

    wx_kernel<<<dim3(G_ / 64, (T_ * N_) / 64), 256, smem_gemm>>>(seq, emb, W, b);
    rec2_kernel<<<GCTA, RTHREADS, smem_rec>>>(mask, topo, U);
    out_kernel<<<dim3((V_ + 63) / 64, N_ / 64), 256, smem_gemm>>>(Wout, bout, out);
}

// round 3
// speedup vs baseline: 1.9338x; 1.6346x over previous
#include <cuda_runtime.h>
#include <math.h>

#define T_ 200
#define N_ 256
#define H_ 128
#define G_ 512   // 4*H
#define V_ 50000

#define TB 10          // time-block size (divides 200)
#define NBLK (T_/TB)   // 20 blocks
#define NB 4           // sequences per CTA
#define GCTA (N_/NB)   // 64 CTAs
#define RTHREADS 512
#define UB 8           // U-load double-buffer depth

typedef unsigned long long ull;

// Scratch (static device globals — allocation-free per harness rules)
__device__ float g_wx[(size_t)T_ * N_ * G_];    // 104.8 MB
__device__ float g_hhist[(size_t)T_ * N_ * H_]; // 26.2 MB
__device__ float g_chist[(size_t)T_ * N_ * H_]; // 26.2 MB
__device__ float g_hmean[N_ * H_];

__device__ __forceinline__ float sigf(float x) { return 1.0f / (1.0f + expf(-x)); }

// ---- packed f32x2 helpers (ptxas never auto-fuses; see SASS_QUICKREF) ----
__device__ __forceinline__ ull pk2(float x, float y) {
    ull r; asm("mov.b64 %0,{%1,%2};" : "=l"(r) : "f"(x), "f"(y)); return r;
}
__device__ __forceinline__ ull f2fma(ull a, ull b, ull c) {
    ull d; asm("fma.rn.f32x2 %0,%1,%2,%3;" : "=l"(d) : "l"(a), "l"(b), "l"(c)); return d;
}
__device__ __forceinline__ float2 up2(ull v) {
    float lo, hi; asm("mov.b64 {%0,%1},%2;" : "=f"(lo), "=f"(hi) : "l"(v));
    float2 r; r.x = lo; r.y = hi; return r;
}

// ---------------------------------------------------------------------------
// Kernel 1: Wx[t*N+n, :] = emb[seq[t,n], :] @ W + b   (f32x2 MAC loop)
// ---------------------------------------------------------------------------
__global__ void __launch_bounds__(256) wx_kernel(const int* __restrict__ seq,
                                                 const float* __restrict__ emb,
                                                 const float* __restrict__ W,
                                                 const float* __restrict__ b)
{
    extern __shared__ float sm[];
    float* As = sm;                 // [64][132]
    float* Bs = sm + 64 * 132;      // [128][64]
    int*   ridx = (int*)(Bs + 128 * 64);

    const int tid = threadIdx.x;
    const int bc = blockIdx.x;
    const int br = blockIdx.y;

    if (tid < 64) ridx[tid] = seq[br * 64 + tid];
    __syncthreads();

    for (int p = tid; p < 64 * 32; p += 256) {
        int r = p >> 5, kq = p & 31;
        float4 v = *(const float4*)(emb + (size_t)ridx[r] * H_ + kq * 4);
        float* dst = As + r * 132 + kq * 4;
        dst[0] = v.x; dst[1] = v.y; dst[2] = v.z; dst[3] = v.w;
    }
    for (int p = tid; p < 128 * 16; p += 256) {
        int k = p >> 4, cq = p & 15;
        *(float4*)(Bs + k * 64 + cq * 4) = *(const float4*)(W + k * G_ + bc * 64 + cq * 4);
    }
    __syncthreads();

    const int ty = tid >> 4, tx = tid & 15;
    const int r0 = ty * 4, c0 = tx * 4;
    ull a01[4], a23[4];
    #pragma unroll
    for (int i = 0; i < 4; i++) { a01[i] = 0ull; a23[i] = 0ull; }

    #pragma unroll 8
    for (int k = 0; k < 128; ++k) {
        ull A0 = pk2(As[(r0 + 0) * 132 + k], As[(r0 + 0) * 132 + k]);
        ull A1 = pk2(As[(r0 + 1) * 132 + k], As[(r0 + 1) * 132 + k]);
        ull A2 = pk2(As[(r0 + 2) * 132 + k], As[(r0 + 2) * 132 + k]);
        ull A3 = pk2(As[(r0 + 3) * 132 + k], As[(r0 + 3) * 132 + k]);
        ulonglong2 bv = *(const ulonglong2*)(Bs + k * 64 + c0);
        a01[0] = f2fma(A0, bv.x, a01[0]); a23[0] = f2fma(A0, bv.y, a23[0]);
        a01[1] = f2fma(A1, bv.x, a01[1]); a23[1] = f2fma(A1, bv.y, a23[1]);
        a01[2] = f2fma(A2, bv.x, a01[2]); a23[2] = f2fma(A2, bv.y, a23[2]);
        a01[3] = f2fma(A3, bv.x, a01[3]); a23[3] = f2fma(A3, bv.y, a23[3]);
    }

    float4 bias = *(const float4*)(b + bc * 64 + c0);
    #pragma unroll
    for (int i = 0; i < 4; i++) {
        int row = br * 64 + r0 + i;
        float2 p01 = up2(a01[i]), p23 = up2(a23[i]);
        float4 o;
        o.x = p01.x + bias.x;
        o.y = p01.y + bias.y;
        o.z = p23.x + bias.z;
        o.w = p23.y + bias.w;
        // streaming store: wx won't fit L2; keep hist/topo resident instead
        __stcs((float4*)(g_wx + (size_t)row * G_ + bc * 64 + c0), o);
    }
}

// ---------------------------------------------------------------------------
// Kernel 2: recurrence v3 — f32x2 packed math, double-buffered U loads,
// streaming hints on wx/topo so the 52MB history stays in L2.
// ---------------------------------------------------------------------------
__global__ void __launch_bounds__(RTHREADS, 1) rec2_kernel(const float* __restrict__ mask,
                                                           const float* __restrict__ topo,
                                                           const float* __restrict__ U)
{
    extern __shared__ float sm[];
    float* topoT = sm;                          // 4*200*12 = 9600
    float* Ph    = topoT + 4 * 200 * 12;        // 5120
    float* Pc    = Ph + TB * NB * H_;           // 5120
    float* ringh = Pc + TB * NB * H_;           // 5120
    float* ringc = ringh + TB * NB * H_;        // 5120
    float* hsumT = ringc + TB * NB * H_;        // 512 ([i][4], 16B rows)
    float* csum  = hsumT + H_ * NB;             // 512
    float* gates = csum + NB * H_;              // 2048

    const int tid  = threadIdx.x;
    const int wid  = tid >> 5;
    const int lane = tid & 31;
    const int n0   = blockIdx.x * NB;

    const int ej = tid >> 7;
    const int eh = tid & 127;
    float hacc = 0.0f, lsum = 0.0f;

    const float* Ucol = U + tid;

    for (int k = 0; k < NBLK; ++k) {
        const int t0 = k * TB;
        const int plen = t0 + TB;

        // ---- topo prefix (streamed; read once) ----
        for (int r = wid; r < TB * NB; r += 16) {
            int tt = r / NB, j = r % NB;
            const float* src = topo + ((size_t)(t0 + tt) * N_ + (n0 + j)) * T_;
            for (int tp = lane; tp < plen; tp += 32)
                topoT[(j * 200 + tp) * 12 + tt] = __ldcs(src + tp);
        }
        __syncthreads();

        // ---- prologue: P[tt][j][:] = sum_{tp<t0} topo * hist (packed f32x2) ----
        if (k == 0) {
            for (int i = tid; i < 2 * TB * NB * H_; i += RTHREADS) Ph[i] = 0.0f;
        } else {
            const int j    = wid >> 2;
            const int hc   = (wid >> 1) & 1;
            const int half = wid & 1;
            const float* hist = hc ? g_chist : g_hhist;
            float* P = hc ? Pc : Ph;
            const int d = half * 64 + lane * 2;
            ull acc2[TB];
            #pragma unroll
            for (int s = 0; s < TB; s++) acc2[s] = 0ull;
            const float* tbase = topoT + (size_t)j * 200 * 12;
            #pragma unroll 4
            for (int tp = 0; tp < t0; ++tp) {
                ull hv = *(const ull*)(hist + ((size_t)tp * N_ + n0 + j) * H_ + d);
                const float* tr = tbase + tp * 12;
                float4 w0 = *(const float4*)(tr);
                float4 w1 = *(const float4*)(tr + 4);
                float2 w2 = *(const float2*)(tr + 8);
                float w[TB] = {w0.x, w0.y, w0.z, w0.w, w1.x, w1.y, w1.z, w1.w, w2.x, w2.y};
                #pragma unroll
                for (int s = 0; s < TB; s++)
                    acc2[s] = f2fma(pk2(w[s], w[s]), hv, acc2[s]);
            }
            #pragma unroll
            for (int s = 0; s < TB; s++)
                *(ull*)(P + (s * NB + j) * H_ + d) = acc2[s];
        }
        __syncthreads();

        // ---- sequential steps within the block ----
        for (int tt = 0; tt < TB; ++tt) {
            const int t = t0 + tt;

            // 1. h_sum / c_sum = P + in-block taps
            {
                float ah = Ph[(tt * NB + ej) * H_ + eh];
                float ac = Pc[(tt * NB + ej) * H_ + eh];
                const float* tb2 = topoT + ((size_t)ej * 200 + t0) * 12 + tt;
                for (int s = 0; s < tt; ++s) {
                    float w = tb2[s * 12];
                    ah += w * ringh[(s * NB + ej) * H_ + eh];
                    ac += w * ringc[(s * NB + ej) * H_ + eh];
                }
                hsumT[eh * NB + ej] = ah;
                csum[ej * H_ + eh] = ac;
            }

            // prefetch (independent of the barrier): first U batch, wx row, mask
            float ubuf[UB];
            #pragma unroll
            for (int ii = 0; ii < UB; ii++) ubuf[ii] = Ucol[(size_t)ii * G_];
            const float* wrow = g_wx + ((size_t)t * N_ + n0) * G_;
            float w0 = __ldcs(wrow + tid);
            float w1 = __ldcs(wrow + G_ + tid);
            float w2 = __ldcs(wrow + 2 * G_ + tid);
            float w3 = __ldcs(wrow + 3 * G_ + tid);
            float m  = mask[t * N_ + n0 + ej];
            __syncthreads();

            // 2. gates = hsum @ U + Wx  (f32x2, double-buffered U)
            {
                ull acc01 = 0ull, acc23 = 0ull;
                #pragma unroll
                for (int i0 = 0; i0 < H_; i0 += UB) {
                    float unext[UB];
                    if (i0 + UB < H_) {
                        #pragma unroll
                        for (int ii = 0; ii < UB; ii++)
                            unext[ii] = Ucol[(size_t)(i0 + UB + ii) * G_];
                    }
                    #pragma unroll
                    for (int ii = 0; ii < UB; ii++) {
                        ulonglong2 hv = *(const ulonglong2*)(hsumT + (i0 + ii) * 4);
                        ull uu = pk2(ubuf[ii], ubuf[ii]);
                        acc01 = f2fma(hv.x, uu, acc01);
                        acc23 = f2fma(hv.y, uu, acc23);
                    }
                    if (i0 + UB < H_) {
                        #pragma unroll
                        for (int ii = 0; ii < UB; ii++) ubuf[ii] = unext[ii];
                    }
                }
                float2 a01 = up2(acc01), a23 = up2(acc23);
                gates[0 * G_ + tid] = a01.x + w0;
                gates[1 * G_ + tid] = a01.y + w1;
                gates[2 * G_ + tid] = a23.x + w2;
                gates[3 * G_ + tid] = a23.y + w3;
            }
            __syncthreads();

            // 3. elementwise cell
            {
                float ig = sigf(gates[ej * G_ + eh]);
                float fg = sigf(gates[ej * G_ + 128 + eh]);
                float og = sigf(gates[ej * G_ + 256 + eh]);
                float gg = tanhf(gates[ej * G_ + 384 + eh]);
                float c  = m * (fg * csum[ej * H_ + eh] + ig * gg);
                float h  = m * (og * tanhf(c));
                ringh[(tt * NB + ej) * H_ + eh] = h;
                ringc[(tt * NB + ej) * H_ + eh] = c;
                g_hhist[((size_t)t * N_ + n0 + ej) * H_ + eh] = h;
                g_chist[((size_t)t * N_ + n0 + ej) * H_ + eh] = c;
                hacc += m * h;
                lsum += m;
            }
            __syncthreads();
        }
    }

    g_hmean[(n0 + ej) * H_ + eh] = hacc / lsum;
}

// ---------------------------------------------------------------------------
// Kernel 3: out = h_mean @ W_out + b_out   (f32x2 MAC loop)
// ---------------------------------------------------------------------------
__global__ void __launch_bounds__(256) out_kernel(const float* __restrict__ Wout,
                                                  const float* __restrict__ bout,
                                                  float* __restrict__ out)
{
    extern __shared__ float sm[];
    float* As = sm;                 // [64][132]
    float* Bs = sm + 64 * 132;      // [128][64]

    const int tid = threadIdx.x;
    const int bc = blockIdx.x;
    const int br = blockIdx.y;
    const int cbase = bc * 64;

    for (int p = tid; p < 64 * 32; p += 256) {
        int r = p >> 5, kq = p & 31;
        float4 v = *(const float4*)(g_hmean + (size_t)(br * 64 + r) * H_ + kq * 4);
        float* dst = As + r * 132 + kq * 4;
        dst[0] = v.x; dst[1] = v.y; dst[2] = v.z; dst[3] = v.w;
    }
    for (int p = tid; p < 128 * 16; p += 256) {
        int k = p >> 4, cq = p & 15;
        int c = cbase + cq * 4;
        float4 v = make_float4(0.f, 0.f, 0.f, 0.f);
        if (c < V_) v = *(const float4*)(Wout + (size_t)k * V_ + c);
        *(float4*)(Bs + k * 64 + cq * 4) = v;
    }
    __syncthreads();

    const int ty = tid >> 4, tx = tid & 15;
    const int r0 = ty * 4, c0 = tx * 4;
    ull a01[4], a23[4];
    #pragma unroll
    for (int i = 0; i < 4; i++) { a01[i] = 0ull; a23[i] = 0ull; }

    #pragma unroll 8
    for (int k = 0; k < 128; ++k) {
        ull A0 = pk2(As[(r0 + 0) * 132 + k], As[(r0 + 0) * 132 + k]);
        ull A1 = pk2(As[(r0 + 1) * 132 + k], As[(r0 + 1) * 132 + k]);
        ull A2 = pk2(As[(r0 + 2) * 132 + k], As[(r0 + 2) * 132 + k]);
        ull A3 = pk2(As[(r0 + 3) * 132 + k], As[(r0 + 3) * 132 + k]);
        ulonglong2 bv = *(const ulonglong2*)(Bs + k * 64 + c0);
        a01[0] = f2fma(A0, bv.x, a01[0]); a23[0] = f2fma(A0, bv.y, a23[0]);
        a01[1] = f2fma(A1, bv.x, a01[1]); a23[1] = f2fma(A1, bv.y, a23[1]);
        a01[2] = f2fma(A2, bv.x, a01[2]); a23[2] = f2fma(A2, bv.y, a23[2]);
        a01[3] = f2fma(A3, bv.x, a01[3]); a23[3] = f2fma(A3, bv.y, a23[3]);
    }

    int c = cbase + c0;
    if (c < V_) {
        float4 bias = *(const float4*)(bout + c);
        #pragma unroll
        for (int i = 0; i < 4; i++) {
            int row = br * 64 + r0 + i;
            float2 p01 = up2(a01[i]), p23 = up2(a23[i]);
            float4 o;
            o.x = p01.x + bias.x;
            o.y = p01.y + bias.y;
            o.z = p23.x + bias.z;
            o.w = p23.y + bias.w;
            *(float4*)(out + (size_t)row * V_ + c) = o;
        }
    }
}

// ---------------------------------------------------------------------------
extern "C" void kernel_launch(void* const* d_in, const int* in_sizes, int n_in,
                              void* d_out, int out_size)
{
    const int*   seq  = (const int*)d_in[0];
    const float* mask = (const float*)d_in[1];
    const float* topo = (const float*)d_in[2];
    const float* W    = (const float*)d_in[3];
    const float* U    = (const float*)d_in[4];
    const float* b    = (const float*)d_in[5];
    const float* emb  = (const float*)d_in[6];
    const float* Wout = (const float*)d_in[7];
    const float* bout = (const float*)d_in[8];
    float* out = (float*)d_out;

    const int smem_gemm = (64 * 132 + 128 * 64 + 64) * 4;
    const int smem_rec  = (4 * 200 * 12 + 4 * TB * NB * H_ + H_ * NB + NB * H_ + NB * G_) * 4;

    cudaFuncSetAttribute(wx_kernel,   cudaFuncAttributeMaxDynamicSharedMemorySize, smem_gemm);
    cudaFuncSetAttribute(out_kernel,  cudaFuncAttributeMaxDynamicSharedMemorySize, smem_gemm);
    cudaFuncSetAttribute(rec2_kernel, cudaFuncAttributeMaxDynamicSharedMemorySize, smem_rec);

    wx_kernel<<<dim3(G_ / 64, (T_ * N_) / 64), 256, smem_gemm>>>(seq, emb, W, b);
    rec2_kernel<<<GCTA, RTHREADS, smem_rec>>>(mask, topo, U);
    out_kernel<<<dim3((V_ + 63) / 64, N_ / 64), 256, smem_gemm>>>(Wout, bout, out);
}